// round 1
// baseline (speedup 1.0000x reference)
#include <cuda_runtime.h>
#include <cuda_bf16.h>

// Problem constants
#define NN      8192
#define GEV     32
#define PER     256      // nodes per event
#define KK      15
#define FIN     4
#define FOUT    4
#define LATD    64
#define HIDD    128

#define H_ELEMS   (NN * LATD)          // 524288
#define XE_ELEMS  (NN * FOUT)          // 32768
#define NKE       (NN * KK)            // 122880
#define XE_OFF    (H_ELEMS)
#define EI_OFF    (H_ELEMS + XE_ELEMS) // 557056

// Device scratch (no allocations allowed)
__device__ float g_h0[NN * LATD];
__device__ float g_h1[NN * LATD];
__device__ int   g_nbr[NN * KK];

// ---------------------------------------------------------------------------
// Kernel 1: space_emb FFN  h = leaky(x@W1+b1)@W2+b2
// 4 threads per row, each owns 16 output columns. grid 128 x 256.
// ---------------------------------------------------------------------------
__global__ void k_space_emb(const float* __restrict__ x,
                            const float* __restrict__ W1, const float* __restrict__ b1,
                            const float* __restrict__ W2, const float* __restrict__ b2,
                            float* __restrict__ hout) {
    __shared__ float sW1[FIN * LATD];
    __shared__ float sb1[LATD];
    __shared__ float sW2[LATD * LATD];
    __shared__ float sb2[LATD];
    int tid = threadIdx.x;
    for (int i = tid; i < FIN * LATD; i += blockDim.x) sW1[i] = W1[i];
    for (int i = tid; i < LATD; i += blockDim.x) { sb1[i] = b1[i]; sb2[i] = b2[i]; }
    for (int i = tid; i < LATD * LATD; i += blockDim.x) sW2[i] = W2[i];
    __syncthreads();

    int row = blockIdx.x * 64 + (tid >> 2);
    int q   = tid & 3;                 // column quarter
    int c0  = q * 16;

    float xi0 = x[row * FIN + 0];
    float xi1 = x[row * FIN + 1];
    float xi2 = x[row * FIN + 2];
    float xi3 = x[row * FIN + 3];

    float acc[16];
#pragma unroll
    for (int c = 0; c < 16; ++c) acc[c] = sb2[c0 + c];

#pragma unroll 4
    for (int j = 0; j < LATD; ++j) {
        float tj = sb1[j]
                 + xi0 * sW1[0 * LATD + j]
                 + xi1 * sW1[1 * LATD + j]
                 + xi2 * sW1[2 * LATD + j]
                 + xi3 * sW1[3 * LATD + j];
        tj = (tj > 0.0f) ? tj : 0.01f * tj;
        const float* w2r = &sW2[j * LATD + c0];
#pragma unroll
        for (int c = 0; c < 16; ++c) acc[c] += tj * w2r[c];
    }
    float* o = &hout[row * LATD + c0];
#pragma unroll
    for (int c = 0; c < 16; ++c) o[c] = acc[c];
}

// ---------------------------------------------------------------------------
// Kernel 2: event-local kNN (k=15) on h[:, :3]. 1 block per event (256 thr).
// Register-resident sorted top-15, strict-< insertion matches lax.top_k
// tie-breaking given ascending j. Writes neighbor list + ei to output.
// ---------------------------------------------------------------------------
__global__ void k_knn(const float* __restrict__ h,
                      int* __restrict__ nbr,
                      float* __restrict__ out_ei) {
    __shared__ float px[PER], py[PER], pz[PER];
    int tid  = threadIdx.x;
    int base = blockIdx.x * PER;
    int gid  = base + tid;

    px[tid] = h[gid * LATD + 0];
    py[tid] = h[gid * LATD + 1];
    pz[tid] = h[gid * LATD + 2];
    __syncthreads();

    float bd[KK];
    int   bi[KK];
#pragma unroll
    for (int s = 0; s < KK; ++s) { bd[s] = 3.0e38f; bi[s] = 0; }

    float xi = px[tid], yi = py[tid], zi = pz[tid];

    for (int j = 0; j < PER; ++j) {
        float dx = __fadd_rn(xi, -px[j]);
        float dy = __fadd_rn(yi, -py[j]);
        float dz = __fadd_rn(zi, -pz[j]);
        float d  = __fadd_rn(__fadd_rn(__fmul_rn(dx, dx), __fmul_rn(dy, dy)),
                             __fmul_rn(dz, dz));
        if (j == tid) d = 3.3e38f;           // exclude self
        if (d < bd[KK - 1]) {
            int gj = base + j;
#pragma unroll
            for (int p = KK - 1; p >= 0; --p) {
                bool shift = (p > 0) && (d < bd[p - 1]);
                bool place = !shift && (d < bd[p]);
                if (shift)      { bd[p] = bd[p - 1]; bi[p] = bi[p - 1]; }
                else if (place) { bd[p] = d;         bi[p] = gj;        }
            }
        }
    }

    float fgid = (float)gid;
#pragma unroll
    for (int s = 0; s < KK; ++s) {
        int e = gid * KK + s;
        nbr[e] = bi[s];
        out_ei[e]       = (float)bi[s];   // src row
        out_ei[NKE + e] = fgid;           // dst row
    }
}

// ---------------------------------------------------------------------------
// Kernel 3: GIN layer.  h_out = h_in + relu((h_in + sum_nbr h_in)@Wa+ba)@Wb+bb
// 256 threads, 4 rows per iteration, 32 rows per block, grid 256.
// Weights in dynamic smem (~68 KB).
// ---------------------------------------------------------------------------
__global__ void k_gin(const float* __restrict__ h_in,
                      float* __restrict__ h_out,
                      const int* __restrict__ nbr,
                      const float* __restrict__ Wa, const float* __restrict__ ba,
                      const float* __restrict__ Wb, const float* __restrict__ bb) {
    extern __shared__ float sm[];
    float* sWa  = sm;                         // 64*128
    float* sWb  = sWa + LATD * HIDD;          // 128*64
    float* sba  = sWb + HIDD * LATD;          // 128
    float* sbb  = sba + HIDD;                 // 64
    float* sm_m = sbb + LATD;                 // 4*64
    float* sm_t = sm_m + 4 * LATD;            // 4*128

    int tid = threadIdx.x;
    for (int i = tid; i < LATD * HIDD; i += blockDim.x) sWa[i] = Wa[i];
    for (int i = tid; i < HIDD * LATD; i += blockDim.x) sWb[i] = Wb[i];
    for (int i = tid; i < HIDD; i += blockDim.x) sba[i] = ba[i];
    for (int i = tid; i < LATD; i += blockDim.x) sbb[i] = bb[i];
    __syncthreads();

    int rowbase = blockIdx.x * 32;
    int rA = tid >> 6;           // 0..3 (phase A/C row)
    int cA = tid & 63;
    int jB = tid & 127;          // phase B column
    int hB = tid >> 7;           // 0..1 (phase B row-pair)

    for (int it = 0; it < 32; it += 4) {
        int i = rowbase + it + rA;

        // Phase A: m = h_i + sum of 15 neighbors (per column)
        float hv = h_in[i * LATD + cA];
        float m  = hv;
        const int* nb = &nbr[i * KK];
#pragma unroll
        for (int s = 0; s < KK; ++s)
            m += h_in[nb[s] * LATD + cA];
        sm_m[rA * LATD + cA] = m;
        __syncthreads();

        // Phase B: t = relu(m @ Wa + ba); each thread one j, two rows
        float t0 = sba[jB], t1 = sba[jB];
        const float* m0 = &sm_m[(2 * hB)     * LATD];
        const float* m1 = &sm_m[(2 * hB + 1) * LATD];
#pragma unroll 8
        for (int k = 0; k < LATD; ++k) {
            float w = sWa[k * HIDD + jB];
            t0 += m0[k] * w;
            t1 += m1[k] * w;
        }
        sm_t[(2 * hB)     * HIDD + jB] = fmaxf(t0, 0.0f);
        sm_t[(2 * hB + 1) * HIDD + jB] = fmaxf(t1, 0.0f);
        __syncthreads();

        // Phase C: out = h_i + t @ Wb + bb
        float acc = sbb[cA];
        const float* tr = &sm_t[rA * HIDD];
#pragma unroll 8
        for (int j = 0; j < HIDD; ++j)
            acc += tr[j] * sWb[j * LATD + cA];
        h_out[i * LATD + cA] = hv + acc;
        __syncthreads();
    }
}

// ---------------------------------------------------------------------------
// Kernel 4: out_emb FFN  x_emb = leaky(h@W1+b1)@W2+b2  (h read from d_out)
// 4 threads per row split the j (hidden) dim; shfl-reduce 4 output features.
// ---------------------------------------------------------------------------
__global__ void k_out_emb(const float* __restrict__ h,
                          const float* __restrict__ W1, const float* __restrict__ b1,
                          const float* __restrict__ W2, const float* __restrict__ b2,
                          float* __restrict__ xe) {
    __shared__ float sW1[LATD * LATD];
    __shared__ float sb1[LATD];
    __shared__ float sW2[LATD * FOUT];
    __shared__ float sb2[FOUT];
    int tid = threadIdx.x;
    for (int i = tid; i < LATD * LATD; i += blockDim.x) sW1[i] = W1[i];
    for (int i = tid; i < LATD; i += blockDim.x) sb1[i] = b1[i];
    for (int i = tid; i < LATD * FOUT; i += blockDim.x) sW2[i] = W2[i];
    if (tid < FOUT) sb2[tid] = b2[tid];
    __syncthreads();

    int row = blockIdx.x * 64 + (tid >> 2);
    int q   = tid & 3;

    const float* hr = &h[row * LATD];
    float hv[LATD];
#pragma unroll
    for (int k = 0; k < LATD; ++k) hv[k] = __ldg(&hr[k]);

    float o0 = 0.f, o1 = 0.f, o2 = 0.f, o3 = 0.f;
    int j0 = q * 16;
#pragma unroll
    for (int jj = 0; jj < 16; ++jj) {
        int j = j0 + jj;
        float tj = sb1[j];
#pragma unroll 8
        for (int k = 0; k < LATD; ++k) tj += hv[k] * sW1[k * LATD + j];
        tj = (tj > 0.0f) ? tj : 0.01f * tj;
        o0 += tj * sW2[j * FOUT + 0];
        o1 += tj * sW2[j * FOUT + 1];
        o2 += tj * sW2[j * FOUT + 2];
        o3 += tj * sW2[j * FOUT + 3];
    }
    // reduce across the 4 lanes that share this row (lanes are 4-aligned)
    o0 += __shfl_xor_sync(0xffffffffu, o0, 1);
    o0 += __shfl_xor_sync(0xffffffffu, o0, 2);
    o1 += __shfl_xor_sync(0xffffffffu, o1, 1);
    o1 += __shfl_xor_sync(0xffffffffu, o1, 2);
    o2 += __shfl_xor_sync(0xffffffffu, o2, 1);
    o2 += __shfl_xor_sync(0xffffffffu, o2, 2);
    o3 += __shfl_xor_sync(0xffffffffu, o3, 1);
    o3 += __shfl_xor_sync(0xffffffffu, o3, 2);
    if (q == 0) {
        float* o = &xe[row * FOUT];
        o[0] = o0 + sb2[0];
        o[1] = o1 + sb2[1];
        o[2] = o2 + sb2[2];
        o[3] = o3 + sb2[3];
    }
}

// ---------------------------------------------------------------------------
extern "C" void kernel_launch(void* const* d_in, const int* in_sizes, int n_in,
                              void* d_out, int out_size) {
    const float* x     = (const float*)d_in[0];
    // d_in[1] = batch (structure known: i/256), d_in[2] = condition (unused)
    const float* W_se1 = (const float*)d_in[3];
    const float* b_se1 = (const float*)d_in[4];
    const float* W_se2 = (const float*)d_in[5];
    const float* b_se2 = (const float*)d_in[6];
    const float* W_g1a = (const float*)d_in[7];
    const float* b_g1a = (const float*)d_in[8];
    const float* W_g1b = (const float*)d_in[9];
    const float* b_g1b = (const float*)d_in[10];
    const float* W_g2a = (const float*)d_in[11];
    const float* b_g2a = (const float*)d_in[12];
    const float* W_g2b = (const float*)d_in[13];
    const float* b_g2b = (const float*)d_in[14];
    const float* W_oe1 = (const float*)d_in[15];
    const float* b_oe1 = (const float*)d_in[16];
    const float* W_oe2 = (const float*)d_in[17];
    const float* b_oe2 = (const float*)d_in[18];

    float* out    = (float*)d_out;
    float* out_h  = out;                 // final h lives here (GIN2 writes it)
    float* out_xe = out + XE_OFF;
    float* out_ei = out + EI_OFF;

    void *p_h0, *p_h1, *p_nbr;
    cudaGetSymbolAddress(&p_h0, g_h0);
    cudaGetSymbolAddress(&p_h1, g_h1);
    cudaGetSymbolAddress(&p_nbr, g_nbr);
    float* h0 = (float*)p_h0;
    float* h1 = (float*)p_h1;
    int*   nb = (int*)p_nbr;

    static const size_t gin_smem =
        (LATD * HIDD + HIDD * LATD + HIDD + LATD + 4 * LATD + 4 * HIDD) * sizeof(float);
    cudaFuncSetAttribute(k_gin, cudaFuncAttributeMaxDynamicSharedMemorySize,
                         (int)gin_smem);

    // 1) space_emb -> h0
    k_space_emb<<<NN / 64, 256>>>(x, W_se1, b_se1, W_se2, b_se2, h0);
    // 2) kNN on h0[:, :3] -> nbr, ei written to output
    k_knn<<<GEV, PER>>>(h0, nb, out_ei);
    // 3) GIN layer 1: h0 -> h1
    k_gin<<<NN / 32, 256, gin_smem>>>(h0, h1, nb, W_g1a, b_g1a, W_g1b, b_g1b);
    // 4) GIN layer 2: h1 -> final h directly into d_out
    k_gin<<<NN / 32, 256, gin_smem>>>(h1, out_h, nb, W_g2a, b_g2a, W_g2b, b_g2b);
    // 5) out_emb: reads final h from d_out, writes x_emb
    k_out_emb<<<NN / 64, 256>>>(out_h, W_oe1, b_oe1, W_oe2, b_oe2, out_xe);
}

// round 2
// speedup vs baseline: 1.4931x; 1.4931x over previous
#include <cuda_runtime.h>
#include <cuda_bf16.h>

// Problem constants
#define NN      8192
#define GEV     32
#define PER     256      // nodes per event
#define KK      15
#define FIN     4
#define FOUT    4
#define LATD    64
#define HIDD    128

#define H_ELEMS   (NN * LATD)          // 524288
#define XE_ELEMS  (NN * FOUT)          // 32768
#define NKE       (NN * KK)            // 122880
#define XE_OFF    (H_ELEMS)
#define EI_OFF    (H_ELEMS + XE_ELEMS) // 557056

#define FULLMASK 0xffffffffu

// Device scratch (no allocations allowed)
__device__ float g_h0[NN * LATD];
__device__ float g_h1[NN * LATD];
__device__ int   g_nbr[NN * KK];

// ---------------------------------------------------------------------------
// Kernel 1: space_emb FFN  h = leaky(x@W1+b1)@W2+b2
// 4 threads per row, each owns 16 output columns. grid 128 x 256.
// ---------------------------------------------------------------------------
__global__ void k_space_emb(const float* __restrict__ x,
                            const float* __restrict__ W1, const float* __restrict__ b1,
                            const float* __restrict__ W2, const float* __restrict__ b2,
                            float* __restrict__ hout) {
    __shared__ float sW1[FIN * LATD];
    __shared__ float sb1[LATD];
    __shared__ float sW2[LATD * LATD];
    __shared__ float sb2[LATD];
    int tid = threadIdx.x;
    for (int i = tid; i < FIN * LATD; i += blockDim.x) sW1[i] = W1[i];
    for (int i = tid; i < LATD; i += blockDim.x) { sb1[i] = b1[i]; sb2[i] = b2[i]; }
    for (int i = tid; i < LATD * LATD; i += blockDim.x) sW2[i] = W2[i];
    __syncthreads();

    int row = blockIdx.x * 64 + (tid >> 2);
    int q   = tid & 3;
    int c0  = q * 16;

    float xi0 = x[row * FIN + 0];
    float xi1 = x[row * FIN + 1];
    float xi2 = x[row * FIN + 2];
    float xi3 = x[row * FIN + 3];

    float acc[16];
#pragma unroll
    for (int c = 0; c < 16; ++c) acc[c] = sb2[c0 + c];

#pragma unroll 4
    for (int j = 0; j < LATD; ++j) {
        float tj = sb1[j]
                 + xi0 * sW1[0 * LATD + j]
                 + xi1 * sW1[1 * LATD + j]
                 + xi2 * sW1[2 * LATD + j]
                 + xi3 * sW1[3 * LATD + j];
        tj = (tj > 0.0f) ? tj : 0.01f * tj;
        const float* w2r = &sW2[j * LATD + c0];
#pragma unroll
        for (int c = 0; c < 16; ++c) acc[c] += tj * w2r[c];
    }
    float* o = &hout[row * LATD + c0];
#pragma unroll
    for (int c = 0; c < 16; ++c) o[c] = acc[c];
}

// ---------------------------------------------------------------------------
// Kernel 2: event-local kNN (k=15) on h[:, :3].
// 4 blocks per event, 64 queries per block, 64 threads. Positions in smem.
// Register-resident sorted top-15, strict-< insertion matches lax.top_k
// tie-breaking given ascending candidate order.
// ---------------------------------------------------------------------------
__global__ void k_knn(const float* __restrict__ h,
                      int* __restrict__ nbr,
                      float* __restrict__ out_ei) {
    __shared__ float px[PER], py[PER], pz[PER];
    int tid  = threadIdx.x;           // 0..63
    int ev   = blockIdx.x >> 2;
    int quad = blockIdx.x & 3;
    int base = ev * PER;

    // cooperatively load the event's 256 positions
#pragma unroll
    for (int s = 0; s < 4; ++s) {
        int n = tid + s * 64;
        px[n] = h[(base + n) * LATD + 0];
        py[n] = h[(base + n) * LATD + 1];
        pz[n] = h[(base + n) * LATD + 2];
    }
    __syncthreads();

    int lq  = quad * 64 + tid;        // local query index in event
    int gid = base + lq;

    float bd[KK];
    int   bi[KK];
#pragma unroll
    for (int s = 0; s < KK; ++s) { bd[s] = 3.0e38f; bi[s] = 0; }

    float xi = px[lq], yi = py[lq], zi = pz[lq];

    for (int j = 0; j < PER; ++j) {
        float dx = __fadd_rn(xi, -px[j]);
        float dy = __fadd_rn(yi, -py[j]);
        float dz = __fadd_rn(zi, -pz[j]);
        float d  = __fadd_rn(__fadd_rn(__fmul_rn(dx, dx), __fmul_rn(dy, dy)),
                             __fmul_rn(dz, dz));
        if (j == lq) d = 3.3e38f;            // exclude self
        if (d < bd[KK - 1]) {
            int gj = base + j;
#pragma unroll
            for (int p = KK - 1; p >= 0; --p) {
                bool shift = (p > 0) && (d < bd[p - 1]);
                bool place = !shift && (d < bd[p]);
                if (shift)      { bd[p] = bd[p - 1]; bi[p] = bi[p - 1]; }
                else if (place) { bd[p] = d;         bi[p] = gj;        }
            }
        }
    }

    float fgid = (float)gid;
#pragma unroll
    for (int s = 0; s < KK; ++s) {
        int e = gid * KK + s;
        nbr[e] = bi[s];
        out_ei[e]       = (float)bi[s];
        out_ei[NKE + e] = fgid;
    }
}

// ---------------------------------------------------------------------------
// Kernel 3: GIN layer, warp-autonomous register-blocked.
// Each warp owns 8 rows end-to-end; m and t live in registers distributed
// across lanes and broadcast via shfl. Weights in smem (one barrier total).
// grid 128 x 256 (8 warps/block, 8 rows/warp).
// ---------------------------------------------------------------------------
__global__ void __launch_bounds__(256, 1)
k_gin(const float* __restrict__ h_in,
      float* __restrict__ h_out,
      const int* __restrict__ nbr,
      const float* __restrict__ Wa, const float* __restrict__ ba,
      const float* __restrict__ Wb, const float* __restrict__ bb) {
    extern __shared__ float sm[];
    float* sWa = sm;                          // 64*128
    float* sWb = sWa + LATD * HIDD;           // 128*64
    float* sba = sWb + HIDD * LATD;           // 128
    float* sbb = sba + HIDD;                  // 64

    int tid = threadIdx.x;
    // vectorized weight load
    {
        const float4* Wa4 = (const float4*)Wa;
        const float4* Wb4 = (const float4*)Wb;
        float4* sWa4 = (float4*)sWa;
        float4* sWb4 = (float4*)sWb;
#pragma unroll
        for (int i = 0; i < (LATD * HIDD) / 4 / 256; ++i) {
            sWa4[tid + i * 256] = Wa4[tid + i * 256];
            sWb4[tid + i * 256] = Wb4[tid + i * 256];
        }
        if (tid < HIDD) sba[tid] = ba[tid];
        if (tid < LATD) sbb[tid] = bb[tid];
    }
    __syncthreads();

    int warp = tid >> 5;
    int lane = tid & 31;
    int base = (blockIdx.x * 8 + warp) * 8;   // first of this warp's 8 rows

    // ---- Phase A: gather. lane owns columns (2*lane, 2*lane+1) of m -------
    float mlo[8], mhi[8];
    const float2* h2 = (const float2*)h_in;
#pragma unroll
    for (int r = 0; r < 8; ++r) {
        int i = base + r;
        const int* nb = &nbr[i * KK];
        float2 a = h2[i * 32 + lane];
        float ax = a.x, ay = a.y;
#pragma unroll
        for (int s = 0; s < KK; ++s) {
            float2 v = h2[nb[s] * 32 + lane];
            ax += v.x; ay += v.y;
        }
        mlo[r] = ax; mhi[r] = ay;
    }

    // ---- Phase B: t = relu(m @ Wa + ba). lane owns j = lane + 32q --------
    float t0[8], t1[8], t2[8], t3[8];
    {
        float bv0 = sba[lane], bv1 = sba[lane + 32];
        float bv2 = sba[lane + 64], bv3 = sba[lane + 96];
#pragma unroll
        for (int r = 0; r < 8; ++r) { t0[r] = bv0; t1[r] = bv1; t2[r] = bv2; t3[r] = bv3; }
    }
#pragma unroll 4
    for (int k2 = 0; k2 < 32; ++k2) {
#pragma unroll
        for (int kk = 0; kk < 2; ++kk) {
            int k = 2 * k2 + kk;
            const float* wr = &sWa[k * HIDD + lane];
            float w0 = wr[0], w1 = wr[32], w2 = wr[64], w3 = wr[96];
#pragma unroll
            for (int r = 0; r < 8; ++r) {
                float mk = __shfl_sync(FULLMASK, kk ? mhi[r] : mlo[r], k2);
                t0[r] += mk * w0;
                t1[r] += mk * w1;
                t2[r] += mk * w2;
                t3[r] += mk * w3;
            }
        }
    }
#pragma unroll
    for (int r = 0; r < 8; ++r) {
        t0[r] = fmaxf(t0[r], 0.0f);
        t1[r] = fmaxf(t1[r], 0.0f);
        t2[r] = fmaxf(t2[r], 0.0f);
        t3[r] = fmaxf(t3[r], 0.0f);
    }

    // ---- Phase C: out = h + t @ Wb + bb. lane owns c = lane, lane+32 -----
    float o0[8], o1[8];
    {
        float bv0 = sbb[lane], bv1 = sbb[lane + 32];
#pragma unroll
        for (int r = 0; r < 8; ++r) { o0[r] = bv0; o1[r] = bv1; }
    }
#pragma unroll
    for (int q = 0; q < 4; ++q) {
#pragma unroll 4
        for (int jj = 0; jj < 32; ++jj) {
            int j = q * 32 + jj;
            const float* wr = &sWb[j * LATD + lane];
            float w0 = wr[0], w1 = wr[32];
#pragma unroll
            for (int r = 0; r < 8; ++r) {
                float tv = (q == 0) ? t0[r] : (q == 1) ? t1[r] : (q == 2) ? t2[r] : t3[r];
                float tj = __shfl_sync(FULLMASK, tv, jj);
                o0[r] += tj * w0;
                o1[r] += tj * w1;
            }
        }
    }
#pragma unroll
    for (int r = 0; r < 8; ++r) {
        int i = base + r;
        h_out[i * LATD + lane]      = h_in[i * LATD + lane]      + o0[r];
        h_out[i * LATD + lane + 32] = h_in[i * LATD + lane + 32] + o1[r];
    }
}

// ---------------------------------------------------------------------------
// Kernel 4: out_emb FFN  x_emb = leaky(h@W1+b1)@W2+b2  (h read from d_out)
// 4 threads per row split the j (hidden) dim; shfl-reduce 4 output features.
// ---------------------------------------------------------------------------
__global__ void k_out_emb(const float* __restrict__ h,
                          const float* __restrict__ W1, const float* __restrict__ b1,
                          const float* __restrict__ W2, const float* __restrict__ b2,
                          float* __restrict__ xe) {
    __shared__ float sW1[LATD * LATD];
    __shared__ float sb1[LATD];
    __shared__ float sW2[LATD * FOUT];
    __shared__ float sb2[FOUT];
    int tid = threadIdx.x;
    for (int i = tid; i < LATD * LATD; i += blockDim.x) sW1[i] = W1[i];
    for (int i = tid; i < LATD; i += blockDim.x) sb1[i] = b1[i];
    for (int i = tid; i < LATD * FOUT; i += blockDim.x) sW2[i] = W2[i];
    if (tid < FOUT) sb2[tid] = b2[tid];
    __syncthreads();

    int row = blockIdx.x * 64 + (tid >> 2);
    int q   = tid & 3;

    const float* hr = &h[row * LATD];
    float hv[LATD];
#pragma unroll
    for (int k = 0; k < LATD; ++k) hv[k] = __ldg(&hr[k]);

    float o0 = 0.f, o1 = 0.f, o2 = 0.f, o3 = 0.f;
    int j0 = q * 16;
#pragma unroll
    for (int jj = 0; jj < 16; ++jj) {
        int j = j0 + jj;
        float tj = sb1[j];
#pragma unroll 8
        for (int k = 0; k < LATD; ++k) tj += hv[k] * sW1[k * LATD + j];
        tj = (tj > 0.0f) ? tj : 0.01f * tj;
        o0 += tj * sW2[j * FOUT + 0];
        o1 += tj * sW2[j * FOUT + 1];
        o2 += tj * sW2[j * FOUT + 2];
        o3 += tj * sW2[j * FOUT + 3];
    }
    o0 += __shfl_xor_sync(FULLMASK, o0, 1);
    o0 += __shfl_xor_sync(FULLMASK, o0, 2);
    o1 += __shfl_xor_sync(FULLMASK, o1, 1);
    o1 += __shfl_xor_sync(FULLMASK, o1, 2);
    o2 += __shfl_xor_sync(FULLMASK, o2, 1);
    o2 += __shfl_xor_sync(FULLMASK, o2, 2);
    o3 += __shfl_xor_sync(FULLMASK, o3, 1);
    o3 += __shfl_xor_sync(FULLMASK, o3, 2);
    if (q == 0) {
        float* o = &xe[row * FOUT];
        o[0] = o0 + sb2[0];
        o[1] = o1 + sb2[1];
        o[2] = o2 + sb2[2];
        o[3] = o3 + sb2[3];
    }
}

// ---------------------------------------------------------------------------
extern "C" void kernel_launch(void* const* d_in, const int* in_sizes, int n_in,
                              void* d_out, int out_size) {
    const float* x     = (const float*)d_in[0];
    const float* W_se1 = (const float*)d_in[3];
    const float* b_se1 = (const float*)d_in[4];
    const float* W_se2 = (const float*)d_in[5];
    const float* b_se2 = (const float*)d_in[6];
    const float* W_g1a = (const float*)d_in[7];
    const float* b_g1a = (const float*)d_in[8];
    const float* W_g1b = (const float*)d_in[9];
    const float* b_g1b = (const float*)d_in[10];
    const float* W_g2a = (const float*)d_in[11];
    const float* b_g2a = (const float*)d_in[12];
    const float* W_g2b = (const float*)d_in[13];
    const float* b_g2b = (const float*)d_in[14];
    const float* W_oe1 = (const float*)d_in[15];
    const float* b_oe1 = (const float*)d_in[16];
    const float* W_oe2 = (const float*)d_in[17];
    const float* b_oe2 = (const float*)d_in[18];

    float* out    = (float*)d_out;
    float* out_h  = out;
    float* out_xe = out + XE_OFF;
    float* out_ei = out + EI_OFF;

    void *p_h0, *p_h1, *p_nbr;
    cudaGetSymbolAddress(&p_h0, g_h0);
    cudaGetSymbolAddress(&p_h1, g_h1);
    cudaGetSymbolAddress(&p_nbr, g_nbr);
    float* h0 = (float*)p_h0;
    float* h1 = (float*)p_h1;
    int*   nb = (int*)p_nbr;

    static const size_t gin_smem =
        (LATD * HIDD + HIDD * LATD + HIDD + LATD) * sizeof(float);
    cudaFuncSetAttribute(k_gin, cudaFuncAttributeMaxDynamicSharedMemorySize,
                         (int)gin_smem);

    // 1) space_emb -> h0
    k_space_emb<<<NN / 64, 256>>>(x, W_se1, b_se1, W_se2, b_se2, h0);
    // 2) kNN on h0[:, :3] -> nbr, ei written to output
    k_knn<<<GEV * 4, 64>>>(h0, nb, out_ei);
    // 3) GIN layer 1: h0 -> h1
    k_gin<<<NN / 64, 256, gin_smem>>>(h0, h1, nb, W_g1a, b_g1a, W_g1b, b_g1b);
    // 4) GIN layer 2: h1 -> final h directly into d_out
    k_gin<<<NN / 64, 256, gin_smem>>>(h1, out_h, nb, W_g2a, b_g2a, W_g2b, b_g2b);
    // 5) out_emb: reads final h from d_out, writes x_emb
    k_out_emb<<<NN / 64, 256>>>(out_h, W_oe1, b_oe1, W_oe2, b_oe2, out_xe);
}

// round 3
// speedup vs baseline: 2.1628x; 1.4485x over previous
#include <cuda_runtime.h>
#include <cuda_bf16.h>

// Problem constants
#define NN      8192
#define GEV     32
#define PER     256      // nodes per event
#define KK      15
#define FIN     4
#define FOUT    4
#define LATD    64
#define HIDD    128

#define H_ELEMS   (NN * LATD)          // 524288
#define XE_ELEMS  (NN * FOUT)          // 32768
#define NKE       (NN * KK)            // 122880
#define XE_OFF    (H_ELEMS)
#define EI_OFF    (H_ELEMS + XE_ELEMS) // 557056

#define FULLMASK 0xffffffffu

// Device scratch (no allocations allowed)
__device__ float g_h0[NN * LATD];
__device__ float g_h1[NN * LATD];
__device__ int   g_nbr[NN * KK];

// ---------------------------------------------------------------------------
// Kernel 1: space_emb FFN  h = leaky(x@W1+b1)@W2+b2
// 4 threads per row, each owns 16 output columns. grid 128 x 256.
// ---------------------------------------------------------------------------
__global__ void k_space_emb(const float* __restrict__ x,
                            const float* __restrict__ W1, const float* __restrict__ b1,
                            const float* __restrict__ W2, const float* __restrict__ b2,
                            float* __restrict__ hout) {
    __shared__ float sW1[FIN * LATD];
    __shared__ float sb1[LATD];
    __shared__ float sW2[LATD * LATD];
    __shared__ float sb2[LATD];
    int tid = threadIdx.x;
    for (int i = tid; i < FIN * LATD; i += blockDim.x) sW1[i] = W1[i];
    for (int i = tid; i < LATD; i += blockDim.x) { sb1[i] = b1[i]; sb2[i] = b2[i]; }
    for (int i = tid; i < LATD * LATD; i += blockDim.x) sW2[i] = W2[i];
    __syncthreads();

    int row = blockIdx.x * 64 + (tid >> 2);
    int q   = tid & 3;
    int c0  = q * 16;

    float xi0 = x[row * FIN + 0];
    float xi1 = x[row * FIN + 1];
    float xi2 = x[row * FIN + 2];
    float xi3 = x[row * FIN + 3];

    float acc[16];
#pragma unroll
    for (int c = 0; c < 16; ++c) acc[c] = sb2[c0 + c];

#pragma unroll 4
    for (int j = 0; j < LATD; ++j) {
        float tj = sb1[j]
                 + xi0 * sW1[0 * LATD + j]
                 + xi1 * sW1[1 * LATD + j]
                 + xi2 * sW1[2 * LATD + j]
                 + xi3 * sW1[3 * LATD + j];
        tj = (tj > 0.0f) ? tj : 0.01f * tj;
        const float* w2r = &sW2[j * LATD + c0];
#pragma unroll
        for (int c = 0; c < 16; ++c) acc[c] += tj * w2r[c];
    }
    float* o = &hout[row * LATD + c0];
#pragma unroll
    for (int c = 0; c < 16; ++c) o[c] = acc[c];
}

// ---------------------------------------------------------------------------
// Kernel 2: event-local kNN (k=15) on h[:, :3].
// 4 blocks per event, 64 queries per block, 128 threads: 2 threads per query
// (even/odd candidate strides), each keeps a sorted top-15, then a smem merge
// with (distance, index) lexicographic order — matches lax.top_k tie-breaking.
// ---------------------------------------------------------------------------
__global__ void k_knn(const float* __restrict__ h,
                      int* __restrict__ nbr,
                      float* __restrict__ out_ei) {
    __shared__ float px[PER], py[PER], pz[PER];
    __shared__ float md[128][KK];
    __shared__ int   mi[128][KK];

    int tid  = threadIdx.x;           // 0..127
    int ev   = blockIdx.x >> 2;
    int quad = blockIdx.x & 3;
    int base = ev * PER;

    // cooperatively load the event's 256 positions
#pragma unroll
    for (int s = 0; s < 2; ++s) {
        int n = tid + s * 128;
        px[n] = h[(base + n) * LATD + 0];
        py[n] = h[(base + n) * LATD + 1];
        pz[n] = h[(base + n) * LATD + 2];
    }
    __syncthreads();

    int lq   = quad * 64 + (tid >> 1); // local query index in event
    int half = tid & 1;                // candidate parity

    float bd[KK];
    int   bi[KK];
#pragma unroll
    for (int s = 0; s < KK; ++s) { bd[s] = 3.0e38f; bi[s] = 0; }

    float xi = px[lq], yi = py[lq], zi = pz[lq];

    for (int j = half; j < PER; j += 2) {
        float dx = __fadd_rn(xi, -px[j]);
        float dy = __fadd_rn(yi, -py[j]);
        float dz = __fadd_rn(zi, -pz[j]);
        float d  = __fadd_rn(__fadd_rn(__fmul_rn(dx, dx), __fmul_rn(dy, dy)),
                             __fmul_rn(dz, dz));
        if (j == lq) d = 3.3e38f;            // exclude self
        if (d < bd[KK - 1]) {
#pragma unroll
            for (int p = KK - 1; p >= 0; --p) {
                bool shift = (p > 0) && (d < bd[p - 1]);
                bool place = !shift && (d < bd[p]);
                if (shift)      { bd[p] = bd[p - 1]; bi[p] = bi[p - 1]; }
                else if (place) { bd[p] = d;         bi[p] = j;         }
            }
        }
    }
#pragma unroll
    for (int s = 0; s < KK; ++s) { md[tid][s] = bd[s]; mi[tid][s] = bi[s]; }
    __syncthreads();

    // merge: thread t (<64) merges rows 2t (even j) and 2t+1 (odd j)
    if (tid < 64) {
        int q   = quad * 64 + tid;
        int gid = base + q;
        float fgid = (float)gid;
        int a = 0, b = 0;
        int ra = 2 * tid, rb = 2 * tid + 1;
#pragma unroll
        for (int s = 0; s < KK; ++s) {
            float da = md[ra][a], db = md[rb][b];
            int   ia = mi[ra][a], ib = mi[rb][b];
            bool takeA = (da < db) || (da == db && ia < ib);
            int  pick  = takeA ? ia : ib;
            if (takeA) ++a; else ++b;
            int gj = base + pick;
            int e  = gid * KK + s;
            nbr[e] = gj;
            out_ei[e]       = (float)gj;
            out_ei[NKE + e] = fgid;
        }
    }
}

// ---------------------------------------------------------------------------
// Kernel 3: GIN layer, warp-autonomous register-blocked.
// 512 threads, 16 warps, 4 rows per warp, grid 128 (64 rows/block).
// m and t live in lane-distributed registers, broadcast via shfl.
// FUSE_OE: gin2 computes x_emb in an epilogue from the register-resident h.
// ---------------------------------------------------------------------------
template <bool FUSE_OE>
__global__ void __launch_bounds__(512, 1)
k_gin(const float* __restrict__ h_in,
      float* __restrict__ h_out,
      const int* __restrict__ nbr,
      const float* __restrict__ Wa, const float* __restrict__ ba,
      const float* __restrict__ Wb, const float* __restrict__ bb,
      const float* __restrict__ W1o, const float* __restrict__ b1o,
      const float* __restrict__ W2o, const float* __restrict__ b2o,
      float* __restrict__ xe) {
    extern __shared__ float sm[];
    float* sWa  = sm;                          // 64*128
    float* sWb  = sWa + LATD * HIDD;           // 128*64
    float* sba  = sWb + HIDD * LATD;           // 128
    float* sbb  = sba + HIDD;                  // 64
    float* sW1o = sbb + LATD;                  // 64*64 (FUSE_OE)
    float* sb1o = sW1o + LATD * LATD;          // 64
    float* sW2o = sb1o + LATD;                 // 64*4
    float* sb2o = sW2o + LATD * FOUT;          // 4

    int tid = threadIdx.x;
    {
        const float4* Wa4 = (const float4*)Wa;
        const float4* Wb4 = (const float4*)Wb;
        float4* sWa4 = (float4*)sWa;
        float4* sWb4 = (float4*)sWb;
#pragma unroll
        for (int i = 0; i < (LATD * HIDD) / 4 / 512; ++i) {
            sWa4[tid + i * 512] = Wa4[tid + i * 512];
            sWb4[tid + i * 512] = Wb4[tid + i * 512];
        }
        if (tid < HIDD) sba[tid] = ba[tid];
        if (tid < LATD) sbb[tid] = bb[tid];
        if (FUSE_OE) {
            const float4* W1o4 = (const float4*)W1o;
            float4* sW1o4 = (float4*)sW1o;
#pragma unroll
            for (int i = 0; i < (LATD * LATD) / 4 / 512; ++i)
                sW1o4[tid + i * 512] = W1o4[tid + i * 512];
            if (tid < LATD) sb1o[tid] = b1o[tid];
            if (tid < LATD * FOUT) sW2o[tid] = W2o[tid];
            if (tid < FOUT) sb2o[tid] = b2o[tid];
        }
    }
    __syncthreads();

    int warp = tid >> 5;
    int lane = tid & 31;
    int base = blockIdx.x * 64 + warp * 4;    // first of this warp's 4 rows

    // ---- Phase A: gather. lane owns columns (2*lane, 2*lane+1) of m -------
    float mlo[4], mhi[4];
    const float2* h2 = (const float2*)h_in;
#pragma unroll
    for (int r = 0; r < 4; ++r) {
        int i = base + r;
        const int* nb = &nbr[i * KK];
        float2 a = h2[i * 32 + lane];
        float ax = a.x, ay = a.y;
#pragma unroll
        for (int s = 0; s < KK; ++s) {
            float2 v = h2[nb[s] * 32 + lane];
            ax += v.x; ay += v.y;
        }
        mlo[r] = ax; mhi[r] = ay;
    }

    // ---- Phase B: t = relu(m @ Wa + ba). lane owns j = lane + 32q --------
    float t0[4], t1[4], t2[4], t3[4];
    {
        float bv0 = sba[lane], bv1 = sba[lane + 32];
        float bv2 = sba[lane + 64], bv3 = sba[lane + 96];
#pragma unroll
        for (int r = 0; r < 4; ++r) { t0[r] = bv0; t1[r] = bv1; t2[r] = bv2; t3[r] = bv3; }
    }
#pragma unroll 4
    for (int k2 = 0; k2 < 32; ++k2) {
#pragma unroll
        for (int kk = 0; kk < 2; ++kk) {
            int k = 2 * k2 + kk;
            const float* wr = &sWa[k * HIDD + lane];
            float w0 = wr[0], w1 = wr[32], w2 = wr[64], w3 = wr[96];
#pragma unroll
            for (int r = 0; r < 4; ++r) {
                float mk = __shfl_sync(FULLMASK, kk ? mhi[r] : mlo[r], k2);
                t0[r] += mk * w0;
                t1[r] += mk * w1;
                t2[r] += mk * w2;
                t3[r] += mk * w3;
            }
        }
    }
#pragma unroll
    for (int r = 0; r < 4; ++r) {
        t0[r] = fmaxf(t0[r], 0.0f);
        t1[r] = fmaxf(t1[r], 0.0f);
        t2[r] = fmaxf(t2[r], 0.0f);
        t3[r] = fmaxf(t3[r], 0.0f);
    }

    // ---- Phase C: out = h + t @ Wb + bb. lane owns c = lane, lane+32 -----
    float o0[4], o1[4];
    {
        float bv0 = sbb[lane], bv1 = sbb[lane + 32];
#pragma unroll
        for (int r = 0; r < 4; ++r) { o0[r] = bv0; o1[r] = bv1; }
    }
#pragma unroll
    for (int q = 0; q < 4; ++q) {
#pragma unroll 4
        for (int jj = 0; jj < 32; ++jj) {
            int j = q * 32 + jj;
            const float* wr = &sWb[j * LATD + lane];
            float w0 = wr[0], w1 = wr[32];
#pragma unroll
            for (int r = 0; r < 4; ++r) {
                float tv = (q == 0) ? t0[r] : (q == 1) ? t1[r] : (q == 2) ? t2[r] : t3[r];
                float tj = __shfl_sync(FULLMASK, tv, jj);
                o0[r] += tj * w0;
                o1[r] += tj * w1;
            }
        }
    }

    // final h for this warp's rows (lane owns columns lane, lane+32)
    float hf0[4], hf1[4];
#pragma unroll
    for (int r = 0; r < 4; ++r) {
        int i = base + r;
        hf0[r] = h_in[i * LATD + lane]      + o0[r];
        hf1[r] = h_in[i * LATD + lane + 32] + o1[r];
        h_out[i * LATD + lane]      = hf0[r];
        h_out[i * LATD + lane + 32] = hf1[r];
    }

    if (FUSE_OE) {
        // ---- Epilogue: x_emb = leaky(h@W1o+b1o)@W2o+b2o --------------------
        // lane owns hidden units j = lane, lane+32
        float u0[4], u1[4];
        {
            float bv0 = sb1o[lane], bv1 = sb1o[lane + 32];
#pragma unroll
            for (int r = 0; r < 4; ++r) { u0[r] = bv0; u1[r] = bv1; }
        }
#pragma unroll 4
        for (int c = 0; c < LATD; ++c) {
            const float* wr = &sW1o[c * LATD + lane];
            float w0 = wr[0], w1 = wr[32];
#pragma unroll
            for (int r = 0; r < 4; ++r) {
                float hc = (c < 32) ? __shfl_sync(FULLMASK, hf0[r], c)
                                    : __shfl_sync(FULLMASK, hf1[r], c - 32);
                u0[r] += hc * w0;
                u1[r] += hc * w1;
            }
        }
        float wA0 = sW2o[lane * FOUT + 0], wA1 = sW2o[lane * FOUT + 1];
        float wA2 = sW2o[lane * FOUT + 2], wA3 = sW2o[lane * FOUT + 3];
        float wB0 = sW2o[(lane + 32) * FOUT + 0], wB1 = sW2o[(lane + 32) * FOUT + 1];
        float wB2 = sW2o[(lane + 32) * FOUT + 2], wB3 = sW2o[(lane + 32) * FOUT + 3];
#pragma unroll
        for (int r = 0; r < 4; ++r) {
            float a = u0[r]; a = (a > 0.0f) ? a : 0.01f * a;
            float b = u1[r]; b = (b > 0.0f) ? b : 0.01f * b;
            float p0 = a * wA0 + b * wB0;
            float p1 = a * wA1 + b * wB1;
            float p2 = a * wA2 + b * wB2;
            float p3 = a * wA3 + b * wB3;
#pragma unroll
            for (int off = 16; off > 0; off >>= 1) {
                p0 += __shfl_xor_sync(FULLMASK, p0, off);
                p1 += __shfl_xor_sync(FULLMASK, p1, off);
                p2 += __shfl_xor_sync(FULLMASK, p2, off);
                p3 += __shfl_xor_sync(FULLMASK, p3, off);
            }
            if (lane == 0) {
                int i = base + r;
                xe[i * FOUT + 0] = p0 + sb2o[0];
                xe[i * FOUT + 1] = p1 + sb2o[1];
                xe[i * FOUT + 2] = p2 + sb2o[2];
                xe[i * FOUT + 3] = p3 + sb2o[3];
            }
        }
    }
}

// ---------------------------------------------------------------------------
extern "C" void kernel_launch(void* const* d_in, const int* in_sizes, int n_in,
                              void* d_out, int out_size) {
    const float* x     = (const float*)d_in[0];
    const float* W_se1 = (const float*)d_in[3];
    const float* b_se1 = (const float*)d_in[4];
    const float* W_se2 = (const float*)d_in[5];
    const float* b_se2 = (const float*)d_in[6];
    const float* W_g1a = (const float*)d_in[7];
    const float* b_g1a = (const float*)d_in[8];
    const float* W_g1b = (const float*)d_in[9];
    const float* b_g1b = (const float*)d_in[10];
    const float* W_g2a = (const float*)d_in[11];
    const float* b_g2a = (const float*)d_in[12];
    const float* W_g2b = (const float*)d_in[13];
    const float* b_g2b = (const float*)d_in[14];
    const float* W_oe1 = (const float*)d_in[15];
    const float* b_oe1 = (const float*)d_in[16];
    const float* W_oe2 = (const float*)d_in[17];
    const float* b_oe2 = (const float*)d_in[18];

    float* out    = (float*)d_out;
    float* out_h  = out;
    float* out_xe = out + XE_OFF;
    float* out_ei = out + EI_OFF;

    void *p_h0, *p_h1, *p_nbr;
    cudaGetSymbolAddress(&p_h0, g_h0);
    cudaGetSymbolAddress(&p_h1, g_h1);
    cudaGetSymbolAddress(&p_nbr, g_nbr);
    float* h0 = (float*)p_h0;
    float* h1 = (float*)p_h1;
    int*   nb = (int*)p_nbr;

    static const size_t gin_smem_base =
        (LATD * HIDD + HIDD * LATD + HIDD + LATD) * sizeof(float);
    static const size_t gin_smem_oe = gin_smem_base +
        (LATD * LATD + LATD + LATD * FOUT + FOUT) * sizeof(float);
    cudaFuncSetAttribute(k_gin<false>, cudaFuncAttributeMaxDynamicSharedMemorySize,
                         (int)gin_smem_base);
    cudaFuncSetAttribute(k_gin<true>, cudaFuncAttributeMaxDynamicSharedMemorySize,
                         (int)gin_smem_oe);

    // 1) space_emb -> h0
    k_space_emb<<<NN / 64, 256>>>(x, W_se1, b_se1, W_se2, b_se2, h0);
    // 2) kNN on h0[:, :3] -> nbr, ei written to output
    k_knn<<<GEV * 4, 128>>>(h0, nb, out_ei);
    // 3) GIN layer 1: h0 -> h1
    k_gin<false><<<NN / 64, 512, gin_smem_base>>>(h0, h1, nb,
        W_g1a, b_g1a, W_g1b, b_g1b, nullptr, nullptr, nullptr, nullptr, nullptr);
    // 4) GIN layer 2 + fused out_emb: h1 -> d_out (h), x_emb -> d_out
    k_gin<true><<<NN / 64, 512, gin_smem_oe>>>(h1, out_h, nb,
        W_g2a, b_g2a, W_g2b, b_g2b, W_oe1, b_oe1, W_oe2, b_oe2, out_xe);
}